// round 1
// baseline (speedup 1.0000x reference)
#include <cuda_runtime.h>
#include <cuda_bf16.h>
#include <cstdint>
#include <math.h>

// Problem constants
#define BB 4
#define SS 2048
#define DM 1024
#define DH 4096
#define MM 8192           // B*S tokens

// ---------------- device scratch (no allocations allowed) ----------------
__device__ double        g_partial[8192];
__device__ float         g_wscale[4];          // [0]=meanclip(w1) [1]=meanclip(w2) [2]=1/mc1 [3]=1/mc2
__device__ __nv_bfloat16 g_xq [(size_t)MM * DM];
__device__ __nv_bfloat16 g_wq1[(size_t)DH * DM];
__device__ __nv_bfloat16 g_wq2[(size_t)DM * DH];
__device__ __nv_bfloat16 g_q2 [(size_t)MM * DH];
__device__ float         g_h  [(size_t)MM * DH];
__device__ float         g_rowscale1[MM];
__device__ float         g_rowscale2[MM];

// ---------------- helpers ----------------
__device__ __forceinline__ uint32_t pack_bf16(float a, float b) {
    __nv_bfloat162 h = __floats2bfloat162_rn(a, b);
    return *reinterpret_cast<uint32_t*>(&h);
}

__device__ __forceinline__ float block_max(float v, float* sred, int tid, int nthr) {
    #pragma unroll
    for (int o = 16; o > 0; o >>= 1) v = fmaxf(v, __shfl_xor_sync(0xFFFFFFFFu, v, o));
    if ((tid & 31) == 0) sred[tid >> 5] = v;
    __syncthreads();
    int nw = nthr >> 5;
    if (tid < 32) {
        float x = (tid < nw) ? sred[tid] : 0.0f;
        #pragma unroll
        for (int o = 16; o > 0; o >>= 1) x = fmaxf(x, __shfl_xor_sync(0xFFFFFFFFu, x, o));
        if (tid == 0) sred[0] = x;
    }
    __syncthreads();
    float r = sred[0];
    __syncthreads();
    return r;
}

// ---------------- weight mean|w| : partial sums (deterministic) ----------------
__global__ void wsum_partial(const float* __restrict__ w1, const float* __restrict__ w2) {
    __shared__ double sd[256];
    int blk = blockIdx.x;                 // 0..8191, 1024 elems each
    const float* src = (blk < 4096) ? (w1 + (size_t)blk * 1024)
                                    : (w2 + (size_t)(blk - 4096) * 1024);
    int tid = threadIdx.x;                // 256
    float4 v = reinterpret_cast<const float4*>(src)[tid];
    double s = ((double)fabsf(v.x) + (double)fabsf(v.y)) +
               ((double)fabsf(v.z) + (double)fabsf(v.w));
    sd[tid] = s; __syncthreads();
    for (int o = 128; o > 0; o >>= 1) { if (tid < o) sd[tid] += sd[tid + o]; __syncthreads(); }
    if (tid == 0) g_partial[blk] = sd[0];
}

__global__ void wsum_final() {
    __shared__ double sd[256];
    int tid = threadIdx.x;
    for (int a = 0; a < 2; a++) {
        double s = 0.0;
        for (int i = tid; i < 4096; i += 256) s += g_partial[a * 4096 + i];
        sd[tid] = s; __syncthreads();
        for (int o = 128; o > 0; o >>= 1) { if (tid < o) sd[tid] += sd[tid + o]; __syncthreads(); }
        if (tid == 0) {
            float mean = (float)(sd[0] / (4096.0 * 1024.0));
            float mc = fmaxf(mean, 1e-5f);
            g_wscale[a]     = mc;
            g_wscale[2 + a] = 1.0f / mc;
        }
        __syncthreads();
    }
}

// ---------------- ternary weight quantization ----------------
__global__ void quant_w(const float* __restrict__ w, int which) {
    __nv_bfloat16* dst = which ? g_wq2 : g_wq1;
    float sw = g_wscale[2 + which];
    size_t idx = (size_t)blockIdx.x * 1024 + (size_t)threadIdx.x * 4;
    float4 v = *reinterpret_cast<const float4*>(w + idx);
    float q0 = fminf(fmaxf(rintf(v.x * sw), -1.0f), 1.0f);
    float q1 = fminf(fmaxf(rintf(v.y * sw), -1.0f), 1.0f);
    float q2 = fminf(fmaxf(rintf(v.z * sw), -1.0f), 1.0f);
    float q3 = fminf(fmaxf(rintf(v.w * sw), -1.0f), 1.0f);
    uint2 p = make_uint2(pack_bf16(q0, q1), pack_bf16(q2, q3));
    *reinterpret_cast<uint2*>(dst + idx) = p;
}

// ---------------- per-token int8 absmax quant of x ----------------
__global__ void quant_x(const float* __restrict__ x) {
    __shared__ float sred[32];
    int m = blockIdx.x, tid = threadIdx.x;   // 256 threads, 1024 elems
    float4 v = reinterpret_cast<const float4*>(x + (size_t)m * DM)[tid];
    float amax = fmaxf(fmaxf(fabsf(v.x), fabsf(v.y)), fmaxf(fabsf(v.z), fabsf(v.w)));
    amax = block_max(amax, sred, tid, 256);
    float s = 127.0f / fmaxf(amax, 1e-5f);
    float q0 = fminf(fmaxf(rintf(v.x * s), -128.0f), 127.0f);
    float q1 = fminf(fmaxf(rintf(v.y * s), -128.0f), 127.0f);
    float q2 = fminf(fmaxf(rintf(v.z * s), -128.0f), 127.0f);
    float q3 = fminf(fmaxf(rintf(v.w * s), -128.0f), 127.0f);
    uint2 p = make_uint2(pack_bf16(q0, q1), pack_bf16(q2, q3));
    *reinterpret_cast<uint2*>(g_xq + (size_t)m * DM + (size_t)tid * 4) = p;
    if (tid == 0) g_rowscale1[m] = 1.0f / s;
}

// ---------------- depthwise conv3 + SiLU + per-token quant ----------------
__global__ void __launch_bounds__(512) conv_silu_quant(const float* __restrict__ cw,
                                                       const float* __restrict__ cb) {
    __shared__ float ys[DH];
    __shared__ float sred[32];
    int m = blockIdx.x, tid = threadIdx.x;
    int spos = m & (SS - 1);
    const float* h0 = g_h + (size_t)m * DH;
    bool has_m = (spos > 0), has_p = (spos < SS - 1);
    float amax = 0.0f;
    #pragma unroll
    for (int it = 0; it < 8; it++) {
        int c = tid + it * 512;
        float y = cb[c];
        if (has_m) y = fmaf(cw[c * 3 + 0], h0[c - DH], y);
        y = fmaf(cw[c * 3 + 1], h0[c], y);
        if (has_p) y = fmaf(cw[c * 3 + 2], h0[c + DH], y);
        y = y / (1.0f + expf(-y));       // SiLU
        ys[c] = y;
        amax = fmaxf(amax, fabsf(y));
    }
    amax = block_max(amax, sred, tid, 512);
    float s2 = 127.0f / fmaxf(amax, 1e-5f);
    __nv_bfloat16* dst = g_q2 + (size_t)m * DH;
    #pragma unroll
    for (int it = 0; it < 8; it++) {
        int c = tid + it * 512;
        float q = fminf(fmaxf(rintf(ys[c] * s2), -128.0f), 127.0f);
        dst[c] = __float2bfloat16_rn(q);
    }
    if (tid == 0) g_rowscale2[m] = 1.0f / s2;
}

// ---------------- bf16 mma.sync GEMM: C[m,n] = (sum_k A[m,k]*B[n,k]) * rowscale[m] * wscale ----------------
#define BM 128
#define BN 128
#define BK 32
#define ASTR 40   // padded smem row stride (halves): conflict-free fragment LDS

__device__ __forceinline__ void cp_async16(uint32_t saddr, const void* g) {
    asm volatile("cp.async.cg.shared.global [%0], [%1], 16;\n" :: "r"(saddr), "l"(g));
}
__device__ __forceinline__ void cp_commit() { asm volatile("cp.async.commit_group;\n"); }
__device__ __forceinline__ void cp_wait0()  { asm volatile("cp.async.wait_group 0;\n"); }

__device__ __forceinline__ void mma16816(float* d, const uint32_t* a, const uint32_t* b) {
    asm volatile(
        "mma.sync.aligned.m16n8k16.row.col.f32.bf16.bf16.f32 "
        "{%0,%1,%2,%3},{%4,%5,%6,%7},{%8,%9},{%0,%1,%2,%3};\n"
        : "+f"(d[0]), "+f"(d[1]), "+f"(d[2]), "+f"(d[3])
        : "r"(a[0]), "r"(a[1]), "r"(a[2]), "r"(a[3]), "r"(b[0]), "r"(b[1]));
}

template <int KK>
__device__ __forceinline__ void load_tiles(__nv_bfloat16* As, __nv_bfloat16* Bs,
                                           const __nv_bfloat16* Ag, const __nv_bfloat16* Bg,
                                           int kb, int tid) {
    #pragma unroll
    for (int i = 0; i < 2; i++) {
        int c = tid + i * 256;
        int row = c >> 2, kc = (c & 3) * 8;
        uint32_t sa = (uint32_t)__cvta_generic_to_shared(As + row * ASTR + kc);
        uint32_t sb = (uint32_t)__cvta_generic_to_shared(Bs + row * ASTR + kc);
        cp_async16(sa, Ag + (size_t)row * KK + kb + kc);
        cp_async16(sb, Bg + (size_t)row * KK + kb + kc);
    }
    cp_commit();
}

// WHICH=0: A=g_xq B=g_wq1 C=g_h   rs=g_rowscale1 ws=g_wscale[0]
// WHICH=1: A=g_q2 B=g_wq2 C=out   rs=g_rowscale2 ws=g_wscale[1]
template <int WHICH, int NN, int KK>
__global__ void __launch_bounds__(256, 2) gemm_bf16(float* __restrict__ Cout) {
    __shared__ __nv_bfloat16 As[2][BM * ASTR];
    __shared__ __nv_bfloat16 Bs[2][BN * ASTR];

    const __nv_bfloat16* A  = WHICH ? g_q2 : g_xq;
    const __nv_bfloat16* B  = WHICH ? g_wq2 : g_wq1;
    float*               C  = WHICH ? Cout : g_h;
    const float*         rs = WHICH ? g_rowscale2 : g_rowscale1;

    const int tid = threadIdx.x, lane = tid & 31, wid = tid >> 5;
    const int wm = (wid >> 1) * 32, wn = (wid & 1) * 64;
    const int m0 = blockIdx.y * BM, n0 = blockIdx.x * BN;
    const int g = lane >> 2, t = lane & 3;

    const __nv_bfloat16* Ag = A + (size_t)m0 * KK;
    const __nv_bfloat16* Bg = B + (size_t)n0 * KK;

    float acc[2][8][4];
    #pragma unroll
    for (int im = 0; im < 2; im++)
        #pragma unroll
        for (int jn = 0; jn < 8; jn++)
            #pragma unroll
            for (int q = 0; q < 4; q++) acc[im][jn][q] = 0.0f;

    constexpr int KT = KK / BK;
    load_tiles<KK>(As[0], Bs[0], Ag, Bg, 0, tid);

    for (int kt = 0; kt < KT; kt++) {
        const int buf = kt & 1;
        cp_wait0();
        __syncthreads();
        if (kt + 1 < KT) load_tiles<KK>(As[buf ^ 1], Bs[buf ^ 1], Ag, Bg, (kt + 1) * BK, tid);

        #pragma unroll
        for (int ks = 0; ks < 2; ks++) {
            const int kof = ks * 16;
            uint32_t af[2][4], bfr[8][2];
            #pragma unroll
            for (int im = 0; im < 2; im++) {
                const __nv_bfloat16* p = &As[buf][(wm + im * 16 + g) * ASTR + kof + t * 2];
                af[im][0] = *reinterpret_cast<const uint32_t*>(p);
                af[im][1] = *reinterpret_cast<const uint32_t*>(p + 8 * ASTR);
                af[im][2] = *reinterpret_cast<const uint32_t*>(p + 8);
                af[im][3] = *reinterpret_cast<const uint32_t*>(p + 8 * ASTR + 8);
            }
            #pragma unroll
            for (int jn = 0; jn < 8; jn++) {
                const __nv_bfloat16* p = &Bs[buf][(wn + jn * 8 + g) * ASTR + kof + t * 2];
                bfr[jn][0] = *reinterpret_cast<const uint32_t*>(p);
                bfr[jn][1] = *reinterpret_cast<const uint32_t*>(p + 8);
            }
            #pragma unroll
            for (int im = 0; im < 2; im++)
                #pragma unroll
                for (int jn = 0; jn < 8; jn++)
                    mma16816(acc[im][jn], af[im], bfr[jn]);
        }
    }

    // epilogue: dequant scales
    const float ws = g_wscale[WHICH];
    #pragma unroll
    for (int im = 0; im < 2; im++) {
        int r0 = m0 + wm + im * 16 + g;
        float rs0 = rs[r0] * ws;
        float rs1 = rs[r0 + 8] * ws;
        #pragma unroll
        for (int jn = 0; jn < 8; jn++) {
            int cc = n0 + wn + jn * 8 + t * 2;
            float2 v0 = make_float2(acc[im][jn][0] * rs0, acc[im][jn][1] * rs0);
            float2 v1 = make_float2(acc[im][jn][2] * rs1, acc[im][jn][3] * rs1);
            *reinterpret_cast<float2*>(&C[(size_t)r0 * NN + cc]) = v0;
            *reinterpret_cast<float2*>(&C[(size_t)(r0 + 8) * NN + cc]) = v1;
        }
    }
}

// ---------------- launch ----------------
extern "C" void kernel_launch(void* const* d_in, const int* in_sizes, int n_in,
                              void* d_out, int out_size) {
    const float* x  = (const float*)d_in[0];   // [4,2048,1024]
    const float* w1 = (const float*)d_in[1];   // [4096,1024]
    const float* cw = (const float*)d_in[2];   // [4096,1,3]
    const float* cb = (const float*)d_in[3];   // [4096]
    const float* w2 = (const float*)d_in[4];   // [1024,4096]
    float* out = (float*)d_out;                // [4,2048,1024]
    (void)in_sizes; (void)n_in; (void)out_size;

    wsum_partial<<<8192, 256>>>(w1, w2);
    wsum_final<<<1, 256>>>();
    quant_w<<<4096, 256>>>(w1, 0);
    quant_w<<<4096, 256>>>(w2, 1);
    quant_x<<<8192, 256>>>(x);
    gemm_bf16<0, DH, DM><<<dim3(DH / BN, MM / BM), 256>>>(nullptr);
    conv_silu_quant<<<8192, 512>>>(cw, cb);
    gemm_bf16<1, DM, DH><<<dim3(DM / BN, MM / BM), 256>>>(out);
}